// round 1
// baseline (speedup 1.0000x reference)
#include <cuda_runtime.h>
#include <math.h>

// ---------------- problem constants ----------------
constexpr int cH   = 16;     // heads
constexpr int cDH  = 128;    // head dim
constexpr int cRK  = 512;    // kv latent rank
constexpr int cRD  = 64;     // rope dim
constexpr int cB   = 2;
constexpr int cL   = 2048;
constexpr int cE   = 2048;
constexpr int cDQK = cDH + cRD;          // 192
constexpr int cNQ  = cH * cDQK;          // 3072
constexpr int cNKV = cRK + cRD;          // 576
constexpr int cNUP = cH * (2*cDH + cRD); // 5120
constexpr int cM   = cB * cL;            // 4096 rows
constexpr int cBH  = cB * cH;            // 32

// ---------------- scratch (device globals; no allocs allowed) ----------------
__device__ float g_qall[(size_t)cM * cNQ];          // 50 MB
__device__ float g_kv  [(size_t)cM * cNKV];         // 9.4 MB
__device__ float g_up  [(size_t)cM * cNUP];         // 84 MB
__device__ float g_Q   [(size_t)cBH * cL * cDQK];   // 50 MB
__device__ float g_K   [(size_t)cBH * cL * cDQK];   // 50 MB
__device__ float g_V   [(size_t)cBH * cL * cDQK];   // 50 MB
__device__ float g_S   [(size_t)cBH * cL * cL];     // 537 MB
__device__ float g_AO  [(size_t)cM * cNQ];          // 50 MB

// ---------------- tiled SGEMM config ----------------
constexpr int BM = 64, BN = 64, BK = 16;
// 256 threads, each computes a 4x4 micro tile.

// C[M,N] = alpha * A[M,K] @ B[K,N]; all row-major with given leading strides.
// Requires: M%64==0, N%64==0, K%16==0, all row strides %4==0 (for float4).
__global__ void sgemm_nn(const float* __restrict__ A, const float* __restrict__ B,
                         float* __restrict__ C, int M, int N, int K,
                         int lda, int ldb, int ldc, float alpha)
{
    __shared__ float As[BK][BM + 4];
    __shared__ float Bs[BK][BN + 4];
    const int tid = threadIdx.x;
    const int m0 = blockIdx.y * BM;
    const int n0 = blockIdx.x * BN;
    const int tx = tid & 15, ty = tid >> 4;
    const int arow = tid >> 2, acol = (tid & 3) * 4;   // A: 64 rows x 16 cols, float4 along k
    const int brow = tid >> 4, bcol = (tid & 15) * 4;  // B: 16 rows x 64 cols, float4 along n

    float acc[4][4] = {};
    for (int k0 = 0; k0 < K; k0 += BK) {
        float4 av = *reinterpret_cast<const float4*>(&A[(size_t)(m0 + arow) * lda + k0 + acol]);
        As[acol + 0][arow] = av.x; As[acol + 1][arow] = av.y;
        As[acol + 2][arow] = av.z; As[acol + 3][arow] = av.w;
        float4 bv = *reinterpret_cast<const float4*>(&B[(size_t)(k0 + brow) * ldb + n0 + bcol]);
        *reinterpret_cast<float4*>(&Bs[brow][bcol]) = bv;
        __syncthreads();
#pragma unroll
        for (int kk = 0; kk < BK; kk++) {
            float4 a4 = *reinterpret_cast<const float4*>(&As[kk][ty * 4]);
            float4 b4 = *reinterpret_cast<const float4*>(&Bs[kk][tx * 4]);
            float a[4] = {a4.x, a4.y, a4.z, a4.w};
            float b[4] = {b4.x, b4.y, b4.z, b4.w};
#pragma unroll
            for (int i = 0; i < 4; i++)
#pragma unroll
                for (int j = 0; j < 4; j++)
                    acc[i][j] += a[i] * b[j];
        }
        __syncthreads();
    }
#pragma unroll
    for (int i = 0; i < 4; i++) {
        const size_t m = m0 + ty * 4 + i;
#pragma unroll
        for (int j = 0; j < 4; j++)
            C[m * ldc + n0 + tx * 4 + j] = alpha * acc[i][j];
    }
}

// ---------------- RoPE ----------------
__global__ void rope_q_kernel(const float* __restrict__ cosT, const float* __restrict__ sinT)
{
    int idx = blockIdx.x * blockDim.x + threadIdx.x;  // over rows * H * RD/2
    if (idx >= cM * cH * (cRD / 2)) return;
    int i = idx % (cRD / 2);
    int h = (idx / (cRD / 2)) % cH;
    int row = idx / ((cRD / 2) * cH);
    int l = row % cL;
    float c = cosT[l * (cRD / 2) + i];
    float s = sinT[l * (cRD / 2) + i];
    float* p = &g_qall[(size_t)row * cNQ + h * cDQK + cDH + 2 * i];
    float x1 = p[0], x2 = p[1];
    p[0] = x1 * c - x2 * s;
    p[1] = x1 * s + x2 * c;
}

__global__ void rope_k_kernel(const float* __restrict__ cosT, const float* __restrict__ sinT)
{
    int idx = blockIdx.x * blockDim.x + threadIdx.x;  // over rows * RD/2
    if (idx >= cM * (cRD / 2)) return;
    int i = idx % (cRD / 2);
    int row = idx / (cRD / 2);
    int l = row % cL;
    float c = cosT[l * (cRD / 2) + i];
    float s = sinT[l * (cRD / 2) + i];
    float* p = &g_kv[(size_t)row * cNKV + cRK + 2 * i];
    float x1 = p[0], x2 = p[1];
    p[0] = x1 * c - x2 * s;
    p[1] = x1 * s + x2 * c;
}

// ---------------- gather Q/K/V into (bh, l, 192) ----------------
__global__ void build_qkv_kernel()
{
    size_t idx = (size_t)blockIdx.x * blockDim.x + threadIdx.x;
    const size_t total = (size_t)cBH * cL * cDQK;
    if (idx >= total) return;
    int d = (int)(idx % cDQK);
    int l = (int)((idx / cDQK) % cL);
    int bh = (int)(idx / ((size_t)cDQK * cL));
    int b = bh / cH, h = bh % cH;
    size_t row = (size_t)b * cL + l;

    g_Q[idx] = g_qall[row * cNQ + h * cDQK + d];
    float k, v;
    const size_t upo = row * cNUP + (size_t)h * (2 * cDH + cRD);
    if (d < cDH) {
        k = g_up[upo + d];
        v = g_up[upo + cDH + d];
    } else {
        k = g_kv[row * cNKV + cRK + (d - cDH)];
        v = g_up[upo + 2 * cDH + (d - cDH)];
    }
    g_K[idx] = k;
    g_V[idx] = v;
}

// ---------------- scores: S = scale * Q @ K^T (skip fully-masked tiles) ----------------
__global__ void attn_scores_kernel(float alpha)
{
    const int bh = blockIdx.z;
    const int m0 = blockIdx.y * BM;
    const int n0 = blockIdx.x * BN;
    if (n0 >= m0 + BM) return;  // entire tile above the diagonal: softmax writes zeros there

    __shared__ float As[BK][BM + 4];
    __shared__ float Bs[BK][BN + 4];
    const float* A = g_Q + (size_t)bh * cL * cDQK;
    const float* Bm = g_K + (size_t)bh * cL * cDQK;
    float* C = g_S + (size_t)bh * cL * cL;

    const int tid = threadIdx.x;
    const int tx = tid & 15, ty = tid >> 4;
    const int lrow = tid >> 2, lcol = (tid & 3) * 4;

    float acc[4][4] = {};
    for (int k0 = 0; k0 < cDQK; k0 += BK) {
        float4 av = *reinterpret_cast<const float4*>(&A[(size_t)(m0 + lrow) * cDQK + k0 + lcol]);
        As[lcol + 0][lrow] = av.x; As[lcol + 1][lrow] = av.y;
        As[lcol + 2][lrow] = av.z; As[lcol + 3][lrow] = av.w;
        float4 bv = *reinterpret_cast<const float4*>(&Bm[(size_t)(n0 + lrow) * cDQK + k0 + lcol]);
        Bs[lcol + 0][lrow] = bv.x; Bs[lcol + 1][lrow] = bv.y;
        Bs[lcol + 2][lrow] = bv.z; Bs[lcol + 3][lrow] = bv.w;
        __syncthreads();
#pragma unroll
        for (int kk = 0; kk < BK; kk++) {
            float4 a4 = *reinterpret_cast<const float4*>(&As[kk][ty * 4]);
            float4 b4 = *reinterpret_cast<const float4*>(&Bs[kk][tx * 4]);
            float a[4] = {a4.x, a4.y, a4.z, a4.w};
            float b[4] = {b4.x, b4.y, b4.z, b4.w};
#pragma unroll
            for (int i = 0; i < 4; i++)
#pragma unroll
                for (int j = 0; j < 4; j++)
                    acc[i][j] += a[i] * b[j];
        }
        __syncthreads();
    }
#pragma unroll
    for (int i = 0; i < 4; i++) {
        const size_t m = m0 + ty * 4 + i;
#pragma unroll
        for (int j = 0; j < 4; j++)
            C[m * cL + n0 + tx * 4 + j] = alpha * acc[i][j];
    }
}

// ---------------- causal softmax (one block per row; zeros above diagonal) ----------------
__device__ __forceinline__ float blockReduceMax(float v, float* red)
{
    __syncthreads();
    int tid = threadIdx.x;
#pragma unroll
    for (int o = 16; o > 0; o >>= 1) v = fmaxf(v, __shfl_xor_sync(0xffffffffu, v, o));
    if ((tid & 31) == 0) red[tid >> 5] = v;
    __syncthreads();
    if (tid < 32) {
        float w = (tid < (int)(blockDim.x >> 5)) ? red[tid] : -3.0e38f;
#pragma unroll
        for (int o = 16; o > 0; o >>= 1) w = fmaxf(w, __shfl_xor_sync(0xffffffffu, w, o));
        if (tid == 0) red[0] = w;
    }
    __syncthreads();
    return red[0];
}

__device__ __forceinline__ float blockReduceSum(float v, float* red)
{
    __syncthreads();
    int tid = threadIdx.x;
#pragma unroll
    for (int o = 16; o > 0; o >>= 1) v += __shfl_xor_sync(0xffffffffu, v, o);
    if ((tid & 31) == 0) red[tid >> 5] = v;
    __syncthreads();
    if (tid < 32) {
        float w = (tid < (int)(blockDim.x >> 5)) ? red[tid] : 0.0f;
#pragma unroll
        for (int o = 16; o > 0; o >>= 1) w += __shfl_xor_sync(0xffffffffu, w, o);
        if (tid == 0) red[0] = w;
    }
    __syncthreads();
    return red[0];
}

__global__ void softmax_causal_kernel()
{
    const int l = blockIdx.x;
    const int bh = blockIdx.y;
    float* row = g_S + ((size_t)bh * cL + l) * cL;
    const int n = l + 1;
    const int tid = threadIdx.x;
    __shared__ float red[32];

    float mx = -3.0e38f;
    for (int s = tid; s < n; s += blockDim.x) mx = fmaxf(mx, row[s]);
    mx = blockReduceMax(mx, red);

    float sum = 0.0f;
    for (int s = tid; s < n; s += blockDim.x) {
        float e = __expf(row[s] - mx);
        row[s] = e;
        sum += e;
    }
    sum = blockReduceSum(sum, red);
    const float inv = 1.0f / sum;

    for (int s = tid; s < cL; s += blockDim.x)
        row[s] = (s < n) ? row[s] * inv : 0.0f;
}

// ---------------- AV: AO(b, l, h*192..) = P @ V, K-loop bounded by causal structure ----------------
__global__ void attn_av_kernel()
{
    const int bh = blockIdx.z;
    const int b = bh / cH, h = bh % cH;
    const int m0 = blockIdx.y * BM;
    const int n0 = blockIdx.x * BN;

    __shared__ float As[BK][BM + 4];
    __shared__ float Bs[BK][BN + 4];
    const float* A = g_S + (size_t)bh * cL * cL;      // lda = cL
    const float* Bm = g_V + (size_t)bh * cL * cDQK;   // ldb = cDQK
    float* C = g_AO + (size_t)b * cL * cNQ + (size_t)h * cDQK;  // ldc = cNQ

    const int tid = threadIdx.x;
    const int tx = tid & 15, ty = tid >> 4;
    const int arow = tid >> 2, acol = (tid & 3) * 4;
    const int brow = tid >> 4, bcol = (tid & 15) * 4;

    const int Kend = m0 + BM;  // keys beyond this row block are exactly zero in P
    float acc[4][4] = {};
    for (int k0 = 0; k0 < Kend; k0 += BK) {
        float4 av = *reinterpret_cast<const float4*>(&A[(size_t)(m0 + arow) * cL + k0 + acol]);
        As[acol + 0][arow] = av.x; As[acol + 1][arow] = av.y;
        As[acol + 2][arow] = av.z; As[acol + 3][arow] = av.w;
        float4 bv = *reinterpret_cast<const float4*>(&Bm[(size_t)(k0 + brow) * cDQK + n0 + bcol]);
        *reinterpret_cast<float4*>(&Bs[brow][bcol]) = bv;
        __syncthreads();
#pragma unroll
        for (int kk = 0; kk < BK; kk++) {
            float4 a4 = *reinterpret_cast<const float4*>(&As[kk][ty * 4]);
            float4 b4 = *reinterpret_cast<const float4*>(&Bs[kk][tx * 4]);
            float a[4] = {a4.x, a4.y, a4.z, a4.w};
            float b[4] = {b4.x, b4.y, b4.z, b4.w};
#pragma unroll
            for (int i = 0; i < 4; i++)
#pragma unroll
                for (int j = 0; j < 4; j++)
                    acc[i][j] += a[i] * b[j];
        }
        __syncthreads();
    }
#pragma unroll
    for (int i = 0; i < 4; i++) {
        const size_t m = m0 + ty * 4 + i;
#pragma unroll
        for (int j = 0; j < 4; j++)
            C[m * cNQ + n0 + tx * 4 + j] = acc[i][j];
    }
}

// ---------------- launch ----------------
extern "C" void kernel_launch(void* const* d_in, const int* in_sizes, int n_in,
                              void* d_out, int out_size)
{
    const float* x    = (const float*)d_in[0];
    const float* cosT = (const float*)d_in[1];
    const float* sinT = (const float*)d_in[2];
    const float* wq   = (const float*)d_in[3];
    const float* wkvd = (const float*)d_in[4];
    const float* wup  = (const float*)d_in[5];
    const float* wout = (const float*)d_in[6];
    float* out = (float*)d_out;

    float *p_qall, *p_kv, *p_up, *p_ao;
    cudaGetSymbolAddress((void**)&p_qall, g_qall);
    cudaGetSymbolAddress((void**)&p_kv,   g_kv);
    cudaGetSymbolAddress((void**)&p_up,   g_up);
    cudaGetSymbolAddress((void**)&p_ao,   g_AO);

    const float scale = 1.0f / sqrtf((float)cDQK);

    // 1) q_all = x @ wq   (4096 x 3072 x 2048)
    sgemm_nn<<<dim3(cNQ / BN, cM / BM), 256>>>(x, wq, p_qall, cM, cNQ, cE, cE, cNQ, cNQ, 1.0f);
    // 2) kv_lat = x @ wkv_down   (4096 x 576 x 2048)
    sgemm_nn<<<dim3(cNKV / BN, cM / BM), 256>>>(x, wkvd, p_kv, cM, cNKV, cE, cE, cNKV, cNKV, 1.0f);
    // 3) RoPE
    rope_q_kernel<<<(cM * cH * (cRD / 2) + 255) / 256, 256>>>(cosT, sinT);
    rope_k_kernel<<<(cM * (cRD / 2) + 255) / 256, 256>>>(cosT, sinT);
    // 4) up = c_kv @ w_up   (4096 x 5120 x 512, A strided lda=576)
    sgemm_nn<<<dim3(cNUP / BN, cM / BM), 256>>>(p_kv, wup, p_up, cM, cNUP, cRK, cNKV, cNUP, cNUP, 1.0f);
    // 5) gather Q/K/V
    {
        size_t total = (size_t)cBH * cL * cDQK;
        build_qkv_kernel<<<(unsigned)((total + 255) / 256), 256>>>();
    }
    // 6) scores (causal tiles skipped)
    attn_scores_kernel<<<dim3(cL / BN, cL / BM, cBH), 256>>>(scale);
    // 7) softmax (writes zeros above diagonal)
    softmax_causal_kernel<<<dim3(cL, cBH), 256>>>();
    // 8) P @ V (K-loop causally bounded)
    attn_av_kernel<<<dim3(cDQK / BN, cL / BM, cBH), 256>>>();
    // 9) out = AO @ w_out   (4096 x 2048 x 3072)
    sgemm_nn<<<dim3(cE / BN, cM / BM), 256>>>(p_ao, wout, out, cM, cE, cNQ, cNQ, cE, cE, 1.0f);
}

// round 2
// speedup vs baseline: 2.2985x; 2.2985x over previous
#include <cuda_runtime.h>
#include <math.h>
#include <stdint.h>

// ---------------- problem constants ----------------
constexpr int cH   = 16;
constexpr int cDH  = 128;
constexpr int cRK  = 512;
constexpr int cRD  = 64;
constexpr int cB   = 2;
constexpr int cL   = 2048;
constexpr int cE   = 2048;
constexpr int cDQK = cDH + cRD;          // 192
constexpr int cNQ  = cH * cDQK;          // 3072
constexpr int cNKV = cRK + cRD;          // 576
constexpr int cNUP = cH * (2*cDH + cRD); // 5120
constexpr int cM   = cB * cL;            // 4096
constexpr int cBH  = cB * cH;            // 32

// ---------------- scratch ----------------
__device__ float g_qall[(size_t)cM * cNQ];
__device__ float g_kv  [(size_t)cM * cNKV];
__device__ float g_up  [(size_t)cM * cNUP];
__device__ float g_Q   [(size_t)cBH * cL * cDQK];
__device__ float g_K   [(size_t)cBH * cL * cDQK];
__device__ float g_V   [(size_t)cBH * cL * cDQK];
__device__ float g_S   [(size_t)cBH * cL * cL];
__device__ float g_AO  [(size_t)cM * cNQ];

// ---------------- tf32 tensor-core GEMM ----------------
// Block tile 128x64, K-tile 16, 256 threads (8 warps as 4(m) x 2(n)),
// warp tile 32x32 -> 2 m16 frags x 4 n8 frags, mma.m16n8k8 tf32.
constexpr int TBM = 128, TBN = 64, TBK = 16;

__device__ __forceinline__ uint32_t f2tf32(float x) {
    uint32_t u;
    asm("cvt.rna.tf32.f32 %0, %1;" : "=r"(u) : "f"(x));
    return u;
}

__device__ __forceinline__ void mma_tf32(float* d, const uint32_t* a, const uint32_t* b) {
    asm volatile(
        "mma.sync.aligned.m16n8k8.row.col.f32.tf32.tf32.f32 "
        "{%0,%1,%2,%3},{%4,%5,%6,%7},{%8,%9},{%0,%1,%2,%3};"
        : "+f"(d[0]), "+f"(d[1]), "+f"(d[2]), "+f"(d[3])
        : "r"(a[0]), "r"(a[1]), "r"(a[2]), "r"(a[3]), "r"(b[0]), "r"(b[1]));
}

// MODE: 0 = plain GEMM, 1 = attention scores (batched, causal tile skip, B transposed),
//       2 = attention AV (batched, K-loop causally bounded, strided C)
template<int MODE, bool TRANS_B>
__global__ void tgemm(const float* __restrict__ A0, const float* __restrict__ B0,
                      float* __restrict__ C0, int M, int N, int K,
                      int lda, int ldb, int ldc, float alpha)
{
    const int bh = blockIdx.z;
    const float* A = A0;
    const float* B = B0;
    float* C = C0;
    if (MODE == 1) {
        A += (size_t)bh * cL * cDQK;
        B += (size_t)bh * cL * cDQK;
        C += (size_t)bh * cL * cL;
    } else if (MODE == 2) {
        A += (size_t)bh * cL * cL;
        B += (size_t)bh * cL * cDQK;
        C += (size_t)(bh / cH) * cL * cNQ + (size_t)(bh % cH) * cDQK;
    }
    const int m0 = blockIdx.y * TBM;
    const int n0 = blockIdx.x * TBN;
    if (MODE == 1 && n0 >= m0 + TBM) return;   // fully masked tile
    const int Kend = (MODE == 2) ? (m0 + TBM) : K;

    __shared__ uint32_t As[TBM][TBK + 4];   // stride 20 words (80B, 16B aligned)
    __shared__ uint32_t Bs[TBK][TBN + 4];   // stride 68 words (272B, 16B aligned)

    const int tid = threadIdx.x;
    const int lane = tid & 31;
    const int warp = tid >> 5;
    const int wm0 = (warp & 3) * 32;
    const int wn0 = (warp >> 2) * 32;

    float acc[2][4][4];
#pragma unroll
    for (int i = 0; i < 2; i++)
#pragma unroll
        for (int j = 0; j < 4; j++)
#pragma unroll
            for (int r = 0; r < 4; r++) acc[i][j][r] = 0.0f;

    const int ar = tid >> 2, ac = (tid & 3) * 4;      // A: 128 rows x 4 f4-cols (x2)
    const int br = tid >> 4, bc = (tid & 15) * 4;     // B nn: 16 rows x 16 f4-cols
    const int tn = tid >> 2, tk = (tid & 3) * 4;      // B nt: 64 rows x 4 f4-cols

    for (int k0 = 0; k0 < Kend; k0 += TBK) {
        // ---- A tile ----
#pragma unroll
        for (int half = 0; half < 2; half++) {
            const int r = ar + half * 64;
            float4 v = *reinterpret_cast<const float4*>(&A[(size_t)(m0 + r) * lda + k0 + ac]);
            uint4 t = { f2tf32(v.x), f2tf32(v.y), f2tf32(v.z), f2tf32(v.w) };
            *reinterpret_cast<uint4*>(&As[r][ac]) = t;
        }
        // ---- B tile ----
        if (!TRANS_B) {
            float4 v = *reinterpret_cast<const float4*>(&B[(size_t)(k0 + br) * ldb + n0 + bc]);
            uint4 t = { f2tf32(v.x), f2tf32(v.y), f2tf32(v.z), f2tf32(v.w) };
            *reinterpret_cast<uint4*>(&Bs[br][bc]) = t;
        } else {
            float4 v = *reinterpret_cast<const float4*>(&B[(size_t)(n0 + tn) * ldb + k0 + tk]);
            Bs[tk + 0][tn] = f2tf32(v.x);
            Bs[tk + 1][tn] = f2tf32(v.y);
            Bs[tk + 2][tn] = f2tf32(v.z);
            Bs[tk + 3][tn] = f2tf32(v.w);
        }
        __syncthreads();

#pragma unroll
        for (int s = 0; s < 2; s++) {
            const int kc = s * 8 + (lane & 3);
            uint32_t a[2][4], b[4][2];
#pragma unroll
            for (int i = 0; i < 2; i++) {
                const int r0 = wm0 + i * 16 + (lane >> 2);
                a[i][0] = As[r0][kc];
                a[i][1] = As[r0 + 8][kc];
                a[i][2] = As[r0][kc + 4];
                a[i][3] = As[r0 + 8][kc + 4];
            }
#pragma unroll
            for (int j = 0; j < 4; j++) {
                const int col = wn0 + j * 8 + (lane >> 2);
                b[j][0] = Bs[s * 8 + (lane & 3)][col];
                b[j][1] = Bs[s * 8 + 4 + (lane & 3)][col];
            }
#pragma unroll
            for (int i = 0; i < 2; i++)
#pragma unroll
                for (int j = 0; j < 4; j++)
                    mma_tf32(acc[i][j], a[i], b[j]);
        }
        __syncthreads();
    }

    // ---- store (float2, C frag layout) ----
#pragma unroll
    for (int i = 0; i < 2; i++) {
#pragma unroll
        for (int j = 0; j < 4; j++) {
            const int r = m0 + wm0 + i * 16 + (lane >> 2);
            const int c = n0 + wn0 + j * 8 + (lane & 3) * 2;
            float2 v0 = { alpha * acc[i][j][0], alpha * acc[i][j][1] };
            float2 v1 = { alpha * acc[i][j][2], alpha * acc[i][j][3] };
            *reinterpret_cast<float2*>(&C[(size_t)r * ldc + c]) = v0;
            *reinterpret_cast<float2*>(&C[(size_t)(r + 8) * ldc + c]) = v1;
        }
    }
}

// ---------------- RoPE ----------------
__global__ void rope_q_kernel(const float* __restrict__ cosT, const float* __restrict__ sinT)
{
    int idx = blockIdx.x * blockDim.x + threadIdx.x;
    if (idx >= cM * cH * (cRD / 2)) return;
    int i = idx % (cRD / 2);
    int h = (idx / (cRD / 2)) % cH;
    int row = idx / ((cRD / 2) * cH);
    int l = row % cL;
    float c = cosT[l * (cRD / 2) + i];
    float s = sinT[l * (cRD / 2) + i];
    float* p = &g_qall[(size_t)row * cNQ + h * cDQK + cDH + 2 * i];
    float x1 = p[0], x2 = p[1];
    p[0] = x1 * c - x2 * s;
    p[1] = x1 * s + x2 * c;
}

__global__ void rope_k_kernel(const float* __restrict__ cosT, const float* __restrict__ sinT)
{
    int idx = blockIdx.x * blockDim.x + threadIdx.x;
    if (idx >= cM * (cRD / 2)) return;
    int i = idx % (cRD / 2);
    int row = idx / (cRD / 2);
    int l = row % cL;
    float c = cosT[l * (cRD / 2) + i];
    float s = sinT[l * (cRD / 2) + i];
    float* p = &g_kv[(size_t)row * cNKV + cRK + 2 * i];
    float x1 = p[0], x2 = p[1];
    p[0] = x1 * c - x2 * s;
    p[1] = x1 * s + x2 * c;
}

// ---------------- gather Q/K/V ----------------
__global__ void build_qkv_kernel()
{
    size_t idx = (size_t)blockIdx.x * blockDim.x + threadIdx.x;
    const size_t total = (size_t)cBH * cL * cDQK;
    if (idx >= total) return;
    int d = (int)(idx % cDQK);
    int l = (int)((idx / cDQK) % cL);
    int bh = (int)(idx / ((size_t)cDQK * cL));
    int b = bh / cH, h = bh % cH;
    size_t row = (size_t)b * cL + l;

    g_Q[idx] = g_qall[row * cNQ + h * cDQK + d];
    float k, v;
    const size_t upo = row * cNUP + (size_t)h * (2 * cDH + cRD);
    if (d < cDH) {
        k = g_up[upo + d];
        v = g_up[upo + cDH + d];
    } else {
        k = g_kv[row * cNKV + cRK + (d - cDH)];
        v = g_up[upo + 2 * cDH + (d - cDH)];
    }
    g_K[idx] = k;
    g_V[idx] = v;
}

// ---------------- causal softmax ----------------
__device__ __forceinline__ float blockReduceMax(float v, float* red)
{
    __syncthreads();
    int tid = threadIdx.x;
#pragma unroll
    for (int o = 16; o > 0; o >>= 1) v = fmaxf(v, __shfl_xor_sync(0xffffffffu, v, o));
    if ((tid & 31) == 0) red[tid >> 5] = v;
    __syncthreads();
    if (tid < 32) {
        float w = (tid < (int)(blockDim.x >> 5)) ? red[tid] : -3.0e38f;
#pragma unroll
        for (int o = 16; o > 0; o >>= 1) w = fmaxf(w, __shfl_xor_sync(0xffffffffu, w, o));
        if (tid == 0) red[0] = w;
    }
    __syncthreads();
    return red[0];
}

__device__ __forceinline__ float blockReduceSum(float v, float* red)
{
    __syncthreads();
    int tid = threadIdx.x;
#pragma unroll
    for (int o = 16; o > 0; o >>= 1) v += __shfl_xor_sync(0xffffffffu, v, o);
    if ((tid & 31) == 0) red[tid >> 5] = v;
    __syncthreads();
    if (tid < 32) {
        float w = (tid < (int)(blockDim.x >> 5)) ? red[tid] : 0.0f;
#pragma unroll
        for (int o = 16; o > 0; o >>= 1) w += __shfl_xor_sync(0xffffffffu, w, o);
        if (tid == 0) red[0] = w;
    }
    __syncthreads();
    return red[0];
}

__global__ void softmax_causal_kernel()
{
    const int l = blockIdx.x;
    const int bh = blockIdx.y;
    float* row = g_S + ((size_t)bh * cL + l) * cL;
    const int n = l + 1;
    const int tid = threadIdx.x;
    __shared__ float red[32];

    float mx = -3.0e38f;
    for (int s = tid; s < n; s += blockDim.x) mx = fmaxf(mx, row[s]);
    mx = blockReduceMax(mx, red);

    float sum = 0.0f;
    for (int s = tid; s < n; s += blockDim.x) {
        float e = __expf(row[s] - mx);
        row[s] = e;
        sum += e;
    }
    sum = blockReduceSum(sum, red);
    const float inv = 1.0f / sum;

    for (int s = tid; s < cL; s += blockDim.x)
        row[s] = (s < n) ? row[s] * inv : 0.0f;
}

// ---------------- launch ----------------
extern "C" void kernel_launch(void* const* d_in, const int* in_sizes, int n_in,
                              void* d_out, int out_size)
{
    const float* x    = (const float*)d_in[0];
    const float* cosT = (const float*)d_in[1];
    const float* sinT = (const float*)d_in[2];
    const float* wq   = (const float*)d_in[3];
    const float* wkvd = (const float*)d_in[4];
    const float* wup  = (const float*)d_in[5];
    const float* wout = (const float*)d_in[6];
    float* out = (float*)d_out;

    float *p_qall, *p_kv, *p_up, *p_ao, *p_q, *p_k, *p_v, *p_s;
    cudaGetSymbolAddress((void**)&p_qall, g_qall);
    cudaGetSymbolAddress((void**)&p_kv,   g_kv);
    cudaGetSymbolAddress((void**)&p_up,   g_up);
    cudaGetSymbolAddress((void**)&p_ao,   g_AO);
    cudaGetSymbolAddress((void**)&p_q,    g_Q);
    cudaGetSymbolAddress((void**)&p_k,    g_K);
    cudaGetSymbolAddress((void**)&p_v,    g_V);
    cudaGetSymbolAddress((void**)&p_s,    g_S);

    const float scale = 1.0f / sqrtf((float)cDQK);

    // 1) q_all = x @ wq
    tgemm<0, false><<<dim3(cNQ / TBN, cM / TBM, 1), 256>>>(
        x, wq, p_qall, cM, cNQ, cE, cE, cNQ, cNQ, 1.0f);
    // 2) kv_lat = x @ wkv_down
    tgemm<0, false><<<dim3(cNKV / TBN, cM / TBM, 1), 256>>>(
        x, wkvd, p_kv, cM, cNKV, cE, cE, cNKV, cNKV, 1.0f);
    // 3) RoPE
    rope_q_kernel<<<(cM * cH * (cRD / 2) + 255) / 256, 256>>>(cosT, sinT);
    rope_k_kernel<<<(cM * (cRD / 2) + 255) / 256, 256>>>(cosT, sinT);
    // 4) up = c_kv @ w_up
    tgemm<0, false><<<dim3(cNUP / TBN, cM / TBM, 1), 256>>>(
        p_kv, wup, p_up, cM, cNUP, cRK, cNKV, cNUP, cNUP, 1.0f);
    // 5) gather
    {
        size_t total = (size_t)cBH * cL * cDQK;
        build_qkv_kernel<<<(unsigned)((total + 255) / 256), 256>>>();
    }
    // 6) scores = scale * Q @ K^T (causal tiles skipped)
    tgemm<1, true><<<dim3(cL / TBN, cL / TBM, cBH), 256>>>(
        p_q, p_k, p_s, cL, cL, cDQK, cDQK, cDQK, cL, scale);
    // 7) softmax
    softmax_causal_kernel<<<dim3(cL, cBH), 256>>>();
    // 8) AO = P @ V (K-loop causally bounded)
    tgemm<2, false><<<dim3(cDQK / TBN, cL / TBM, cBH), 256>>>(
        p_s, p_v, p_ao, cL, cDQK, cL, cL, cDQK, cNQ, 1.0f);
    // 9) out = AO @ w_out
    tgemm<0, false><<<dim3(cE / TBN, cM / TBM, 1), 256>>>(
        p_ao, wout, out, cM, cE, cNQ, cNQ, cE, cE, 1.0f);
}

// round 3
// speedup vs baseline: 2.7222x; 1.1843x over previous
#include <cuda_runtime.h>
#include <math.h>
#include <stdint.h>

// ---------------- problem constants ----------------
constexpr int cH   = 16;
constexpr int cDH  = 128;
constexpr int cRK  = 512;
constexpr int cRD  = 64;
constexpr int cB   = 2;
constexpr int cL   = 2048;
constexpr int cE   = 2048;
constexpr int cDQK = cDH + cRD;          // 192
constexpr int cNQ  = cH * cDQK;          // 3072
constexpr int cNKV = cRK + cRD;          // 576
constexpr int cNUP = cH * (2*cDH + cRD); // 5120
constexpr int cM   = cB * cL;            // 4096
constexpr int cBH  = cB * cH;            // 32

// ---------------- scratch ----------------
__device__ float g_qall[(size_t)cM * cNQ];
__device__ float g_kv  [(size_t)cM * cNKV];
__device__ float g_up  [(size_t)cM * cNUP];
__device__ float g_Q   [(size_t)cBH * cL * cDQK];
__device__ float g_K   [(size_t)cBH * cL * cDQK];
__device__ float g_V   [(size_t)cBH * cL * cDQK];
__device__ float g_S   [(size_t)cBH * cL * cL];
__device__ float g_AO  [(size_t)cM * cNQ];

// ---------------- tf32 tensor-core GEMM ----------------
constexpr int TBM = 128, TBK = 16;

__device__ __forceinline__ uint32_t f2tf32(float x) {
    uint32_t u;
    asm("cvt.rna.tf32.f32 %0, %1;" : "=r"(u) : "f"(x));
    return u;
}

__device__ __forceinline__ void mma_tf32(float* d, const uint32_t* a, const uint32_t* b) {
    asm volatile(
        "mma.sync.aligned.m16n8k8.row.col.f32.tf32.tf32.f32 "
        "{%0,%1,%2,%3},{%4,%5,%6,%7},{%8,%9},{%0,%1,%2,%3};"
        : "+f"(d[0]), "+f"(d[1]), "+f"(d[2]), "+f"(d[3])
        : "r"(a[0]), "r"(a[1]), "r"(a[2]), "r"(a[3]), "r"(b[0]), "r"(b[1]));
}

// MODE: 0 = plain GEMM, 1 = scores (batched, causal tile skip, B transposed),
//       2 = AV (batched, K-loop causally bounded, strided C)
// Tiles: TBM=128 fixed; TBN_ in {128, 64}; warp tile WM x WN; 256 threads.
template<int MODE, bool TRANS_B, int TBN_, int WM, int WN>
__global__ void __launch_bounds__(256)
tgemm(const float* __restrict__ A0, const float* __restrict__ B0,
      float* __restrict__ C0, int K, int lda, int ldb, int ldc, float alpha)
{
    constexpr int MI = WM / 16;           // m16 frags per warp
    constexpr int NJ = WN / 8;            // n8 frags per warp
    constexpr int WARPS_M = TBM / WM;
    constexpr int BPAD = 8;               // bank-conflict-free stride (mod 32 = 8)

    const int bh = blockIdx.z;
    const float* A = A0;
    const float* B = B0;
    float* C = C0;
    if (MODE == 1) {
        A += (size_t)bh * cL * cDQK;
        B += (size_t)bh * cL * cDQK;
        C += (size_t)bh * cL * cL;
    } else if (MODE == 2) {
        A += (size_t)bh * cL * cL;
        B += (size_t)bh * cL * cDQK;
        C += (size_t)(bh / cH) * cL * cNQ + (size_t)(bh % cH) * cDQK;
    }
    const int m0 = blockIdx.y * TBM;
    const int n0 = blockIdx.x * TBN_;
    if (MODE == 1 && n0 > m0) return;                 // fully masked tile
    const int Kend = (MODE == 2) ? (m0 + TBM) : K;

    __shared__ uint32_t As[2][TBM][TBK + 4];          // stride 20 (conflict-free)
    __shared__ uint32_t Bs[2][TBK][TBN_ + BPAD];      // stride TBN_+8 (conflict-free)

    const int tid  = threadIdx.x;
    const int lane = tid & 31;
    const int warp = tid >> 5;
    const int wm0 = (warp % WARPS_M) * WM;
    const int wn0 = (warp / WARPS_M) * WN;

    float acc[MI][NJ][4];
#pragma unroll
    for (int i = 0; i < MI; i++)
#pragma unroll
        for (int j = 0; j < NJ; j++)
#pragma unroll
            for (int r = 0; r < 4; r++) acc[i][j][r] = 0.0f;

    // global->register staging maps
    const int ar = tid >> 2, ac = (tid & 3) * 4;        // A: 2x (64 rows x 16 cols)
    const int br = tid >> 4, bc128 = (tid & 15) * 8;    // B nn 128: 16 x (16x8)
    const int bc64 = (tid & 15) * 4;                    // B nn 64
    const int tn = tid >> 2, tk = (tid & 3) * 4;        // B nt: 2x (64 rows x 16 cols)

    float4 ra[2], rb[2];

    auto loadG = [&](int k0) {
        ra[0] = *reinterpret_cast<const float4*>(&A[(size_t)(m0 + ar) * lda + k0 + ac]);
        ra[1] = *reinterpret_cast<const float4*>(&A[(size_t)(m0 + ar + 64) * lda + k0 + ac]);
        if (!TRANS_B) {
            if (TBN_ == 128) {
                rb[0] = *reinterpret_cast<const float4*>(&B[(size_t)(k0 + br) * ldb + n0 + bc128]);
                rb[1] = *reinterpret_cast<const float4*>(&B[(size_t)(k0 + br) * ldb + n0 + bc128 + 4]);
            } else {
                rb[0] = *reinterpret_cast<const float4*>(&B[(size_t)(k0 + br) * ldb + n0 + bc64]);
            }
        } else {
            rb[0] = *reinterpret_cast<const float4*>(&B[(size_t)(n0 + tn) * ldb + k0 + tk]);
            rb[1] = *reinterpret_cast<const float4*>(&B[(size_t)(n0 + tn + 64) * ldb + k0 + tk]);
        }
    };
    auto storeS = [&](int buf) {
#pragma unroll
        for (int h = 0; h < 2; h++) {
            uint4 t = { f2tf32(ra[h].x), f2tf32(ra[h].y), f2tf32(ra[h].z), f2tf32(ra[h].w) };
            *reinterpret_cast<uint4*>(&As[buf][ar + h * 64][ac]) = t;
        }
        if (!TRANS_B) {
            if (TBN_ == 128) {
                uint4 t0 = { f2tf32(rb[0].x), f2tf32(rb[0].y), f2tf32(rb[0].z), f2tf32(rb[0].w) };
                uint4 t1 = { f2tf32(rb[1].x), f2tf32(rb[1].y), f2tf32(rb[1].z), f2tf32(rb[1].w) };
                *reinterpret_cast<uint4*>(&Bs[buf][br][bc128]) = t0;
                *reinterpret_cast<uint4*>(&Bs[buf][br][bc128 + 4]) = t1;
            } else {
                uint4 t0 = { f2tf32(rb[0].x), f2tf32(rb[0].y), f2tf32(rb[0].z), f2tf32(rb[0].w) };
                *reinterpret_cast<uint4*>(&Bs[buf][br][bc64]) = t0;
            }
        } else {
            Bs[buf][tk + 0][tn] = f2tf32(rb[0].x);
            Bs[buf][tk + 1][tn] = f2tf32(rb[0].y);
            Bs[buf][tk + 2][tn] = f2tf32(rb[0].z);
            Bs[buf][tk + 3][tn] = f2tf32(rb[0].w);
            Bs[buf][tk + 0][tn + 64] = f2tf32(rb[1].x);
            Bs[buf][tk + 1][tn + 64] = f2tf32(rb[1].y);
            Bs[buf][tk + 2][tn + 64] = f2tf32(rb[1].z);
            Bs[buf][tk + 3][tn + 64] = f2tf32(rb[1].w);
        }
    };

    loadG(0);
    int buf = 0;
    for (int k0 = 0; k0 < Kend; k0 += TBK) {
        storeS(buf);
        __syncthreads();
        if (k0 + TBK < Kend) loadG(k0 + TBK);

#pragma unroll
        for (int s = 0; s < 2; s++) {
            const int kc = s * 8 + (lane & 3);
            uint32_t a[MI][4], b[NJ][2];
#pragma unroll
            for (int i = 0; i < MI; i++) {
                const int r0 = wm0 + i * 16 + (lane >> 2);
                a[i][0] = As[buf][r0][kc];
                a[i][1] = As[buf][r0 + 8][kc];
                a[i][2] = As[buf][r0][kc + 4];
                a[i][3] = As[buf][r0 + 8][kc + 4];
            }
#pragma unroll
            for (int j = 0; j < NJ; j++) {
                const int col = wn0 + j * 8 + (lane >> 2);
                b[j][0] = Bs[buf][s * 8 + (lane & 3)][col];
                b[j][1] = Bs[buf][s * 8 + 4 + (lane & 3)][col];
            }
#pragma unroll
            for (int i = 0; i < MI; i++)
#pragma unroll
                for (int j = 0; j < NJ; j++)
                    mma_tf32(acc[i][j], a[i], b[j]);
        }
        buf ^= 1;
    }

#pragma unroll
    for (int i = 0; i < MI; i++) {
#pragma unroll
        for (int j = 0; j < NJ; j++) {
            const int r = m0 + wm0 + i * 16 + (lane >> 2);
            const int c = n0 + wn0 + j * 8 + (lane & 3) * 2;
            float2 v0 = { alpha * acc[i][j][0], alpha * acc[i][j][1] };
            float2 v1 = { alpha * acc[i][j][2], alpha * acc[i][j][3] };
            *reinterpret_cast<float2*>(&C[(size_t)r * ldc + c]) = v0;
            *reinterpret_cast<float2*>(&C[(size_t)(r + 8) * ldc + c]) = v1;
        }
    }
}

// ---------------- RoPE ----------------
__global__ void rope_q_kernel(const float* __restrict__ cosT, const float* __restrict__ sinT)
{
    int idx = blockIdx.x * blockDim.x + threadIdx.x;
    if (idx >= cM * cH * (cRD / 2)) return;
    int i = idx % (cRD / 2);
    int h = (idx / (cRD / 2)) % cH;
    int row = idx / ((cRD / 2) * cH);
    int l = row % cL;
    float c = cosT[l * (cRD / 2) + i];
    float s = sinT[l * (cRD / 2) + i];
    float* p = &g_qall[(size_t)row * cNQ + h * cDQK + cDH + 2 * i];
    float x1 = p[0], x2 = p[1];
    p[0] = x1 * c - x2 * s;
    p[1] = x1 * s + x2 * c;
}

__global__ void rope_k_kernel(const float* __restrict__ cosT, const float* __restrict__ sinT)
{
    int idx = blockIdx.x * blockDim.x + threadIdx.x;
    if (idx >= cM * (cRD / 2)) return;
    int i = idx % (cRD / 2);
    int row = idx / (cRD / 2);
    int l = row % cL;
    float c = cosT[l * (cRD / 2) + i];
    float s = sinT[l * (cRD / 2) + i];
    float* p = &g_kv[(size_t)row * cNKV + cRK + 2 * i];
    float x1 = p[0], x2 = p[1];
    p[0] = x1 * c - x2 * s;
    p[1] = x1 * s + x2 * c;
}

// ---------------- gather Q/K/V ----------------
__global__ void build_qkv_kernel()
{
    size_t idx = (size_t)blockIdx.x * blockDim.x + threadIdx.x;
    const size_t total = (size_t)cBH * cL * cDQK;
    if (idx >= total) return;
    int d = (int)(idx % cDQK);
    int l = (int)((idx / cDQK) % cL);
    int bh = (int)(idx / ((size_t)cDQK * cL));
    int b = bh / cH, h = bh % cH;
    size_t row = (size_t)b * cL + l;

    g_Q[idx] = g_qall[row * cNQ + h * cDQK + d];
    float k, v;
    const size_t upo = row * cNUP + (size_t)h * (2 * cDH + cRD);
    if (d < cDH) {
        k = g_up[upo + d];
        v = g_up[upo + cDH + d];
    } else {
        k = g_kv[row * cNKV + cRK + (d - cDH)];
        v = g_up[upo + 2 * cDH + (d - cDH)];
    }
    g_K[idx] = k;
    g_V[idx] = v;
}

// ---------------- causal softmax ----------------
__device__ __forceinline__ float blockReduceMax(float v, float* red)
{
    __syncthreads();
    int tid = threadIdx.x;
#pragma unroll
    for (int o = 16; o > 0; o >>= 1) v = fmaxf(v, __shfl_xor_sync(0xffffffffu, v, o));
    if ((tid & 31) == 0) red[tid >> 5] = v;
    __syncthreads();
    if (tid < 32) {
        float w = (tid < (int)(blockDim.x >> 5)) ? red[tid] : -3.0e38f;
#pragma unroll
        for (int o = 16; o > 0; o >>= 1) w = fmaxf(w, __shfl_xor_sync(0xffffffffu, w, o));
        if (tid == 0) red[0] = w;
    }
    __syncthreads();
    return red[0];
}

__device__ __forceinline__ float blockReduceSum(float v, float* red)
{
    __syncthreads();
    int tid = threadIdx.x;
#pragma unroll
    for (int o = 16; o > 0; o >>= 1) v += __shfl_xor_sync(0xffffffffu, v, o);
    if ((tid & 31) == 0) red[tid >> 5] = v;
    __syncthreads();
    if (tid < 32) {
        float w = (tid < (int)(blockDim.x >> 5)) ? red[tid] : 0.0f;
#pragma unroll
        for (int o = 16; o > 0; o >>= 1) w += __shfl_xor_sync(0xffffffffu, w, o);
        if (tid == 0) red[0] = w;
    }
    __syncthreads();
    return red[0];
}

__global__ void softmax_causal_kernel()
{
    const int l = blockIdx.x;
    const int bh = blockIdx.y;
    float* row = g_S + ((size_t)bh * cL + l) * cL;
    const int n = l + 1;
    const int tid = threadIdx.x;
    __shared__ float red[32];

    float mx = -3.0e38f;
    for (int s = tid; s < n; s += blockDim.x) mx = fmaxf(mx, row[s]);
    mx = blockReduceMax(mx, red);

    float sum = 0.0f;
    for (int s = tid; s < n; s += blockDim.x) {
        float e = __expf(row[s] - mx);
        row[s] = e;
        sum += e;
    }
    sum = blockReduceSum(sum, red);
    const float inv = 1.0f / sum;

    for (int s = tid; s < cL; s += blockDim.x)
        row[s] = (s < n) ? row[s] * inv : 0.0f;
}

// ---------------- launch ----------------
extern "C" void kernel_launch(void* const* d_in, const int* in_sizes, int n_in,
                              void* d_out, int out_size)
{
    const float* x    = (const float*)d_in[0];
    const float* cosT = (const float*)d_in[1];
    const float* sinT = (const float*)d_in[2];
    const float* wq   = (const float*)d_in[3];
    const float* wkvd = (const float*)d_in[4];
    const float* wup  = (const float*)d_in[5];
    const float* wout = (const float*)d_in[6];
    float* out = (float*)d_out;

    float *p_qall, *p_kv, *p_up, *p_ao, *p_q, *p_k, *p_v, *p_s;
    cudaGetSymbolAddress((void**)&p_qall, g_qall);
    cudaGetSymbolAddress((void**)&p_kv,   g_kv);
    cudaGetSymbolAddress((void**)&p_up,   g_up);
    cudaGetSymbolAddress((void**)&p_ao,   g_AO);
    cudaGetSymbolAddress((void**)&p_q,    g_Q);
    cudaGetSymbolAddress((void**)&p_k,    g_K);
    cudaGetSymbolAddress((void**)&p_v,    g_V);
    cudaGetSymbolAddress((void**)&p_s,    g_S);

    const float scale = 1.0f / sqrtf((float)cDQK);

    // 1) q_all = x @ wq   (4096 x 3072 x 2048)
    tgemm<0, false, 128, 64, 32><<<dim3(cNQ / 128, cM / TBM, 1), 256>>>(
        x, wq, p_qall, cE, cE, cNQ, cNQ, 1.0f);
    // 2) kv_lat = x @ wkv_down   (4096 x 576 x 2048)
    tgemm<0, false, 64, 32, 32><<<dim3(cNKV / 64, cM / TBM, 1), 256>>>(
        x, wkvd, p_kv, cE, cE, cNKV, cNKV, 1.0f);
    // 3) RoPE
    rope_q_kernel<<<(cM * cH * (cRD / 2) + 255) / 256, 256>>>(cosT, sinT);
    rope_k_kernel<<<(cM * (cRD / 2) + 255) / 256, 256>>>(cosT, sinT);
    // 4) up = c_kv @ w_up   (4096 x 5120 x 512)
    tgemm<0, false, 128, 64, 32><<<dim3(cNUP / 128, cM / TBM, 1), 256>>>(
        p_kv, wup, p_up, cRK, cNKV, cNUP, cNUP, 1.0f);
    // 5) gather
    {
        size_t total = (size_t)cBH * cL * cDQK;
        build_qkv_kernel<<<(unsigned)((total + 255) / 256), 256>>>();
    }
    // 6) scores = scale * Q @ K^T (causal tiles skipped)
    tgemm<1, true, 128, 64, 32><<<dim3(cL / 128, cL / TBM, cBH), 256>>>(
        p_q, p_k, p_s, cDQK, cDQK, cDQK, cL, scale);
    // 7) softmax
    softmax_causal_kernel<<<dim3(cL, cBH), 256>>>();
    // 8) AO = P @ V (K-loop causally bounded)
    tgemm<2, false, 64, 32, 32><<<dim3(cDQK / 64, cL / TBM, cBH), 256>>>(
        p_s, p_v, p_ao, cL, cL, cDQK, cNQ, 1.0f);
    // 9) out = AO @ w_out   (4096 x 2048 x 3072)
    tgemm<0, false, 128, 64, 32><<<dim3(cE / 128, cM / TBM, 1), 256>>>(
        p_ao, wout, out, cNQ, cNQ, cE, cE, 1.0f);
}